// round 1
// baseline (speedup 1.0000x reference)
#include <cuda_runtime.h>
#include <math.h>

// Problem constants
#define B      128
#define L      196
#define DTOP   64
#define DLOW   128
#define NE     512
#define NBOOK  15
#define EPSF   1e-8f
#define INV512 (1.0f/512.0f)

// Tiling
#define BM        32
#define KT        16
#define NTHREADS  256
#define ROWBLOCKS 7   // ceil(196/32)

// Output layout (float32, outputs concatenated in reference return order)
#define QUANT_OFF 0ll
#define QUANT_CNT (4ll*B*L*DLOW)          // 12,845,056
#define DIFF_OFF  (QUANT_OFF + QUANT_CNT) // 12,845,056
#define ID_OFF    (DIFF_OFF + 1)          // 12,845,057
#define ID_CNT    (4ll*B*L)               // 100,352
#define OT_OFF    (ID_OFF + ID_CNT)       // 12,945,409

// Device scratch (static allocation is allowed; cudaMalloc is not)
__device__ float g_q4[B*L*DTOP];                 // top-level quantized codes (B,L,64)
__device__ float g_diff[5*B*ROWBLOCKS];          // per (level,b,rowblock) diff partials
__device__ float g_e2_top[NBOOK*NE];             // ||e||^2 for top codebooks
__device__ float g_e2_lvl[4*NBOOK*NE];           // ||e||^2 for level codebooks
__device__ float g_inve0[NBOOK*NE];              // 1/(||e||+eps) for level-0 books (OT)

// ---------------------------------------------------------------------------
// Codebook column norms
// grid.x: 0..14 -> cb_top book; 15..74 -> cb_lvl book (j*15+t). block: 512 thr.
// ---------------------------------------------------------------------------
__global__ void norms_kernel(const float* __restrict__ cb_top,
                             const float* __restrict__ cb_lvl)
{
    int k = threadIdx.x;
    int book = blockIdx.x;
    if (book < NBOOK) {
        const float* e = cb_top + (size_t)book * DTOP * NE;
        float s = 0.f;
        #pragma unroll 8
        for (int i = 0; i < DTOP; ++i) { float v = e[(size_t)i*NE + k]; s += v*v; }
        g_e2_top[book*NE + k] = s;
    } else {
        int bl = book - NBOOK;  // j*15 + t
        const float* e = cb_lvl + (size_t)bl * DLOW * NE;
        float s = 0.f;
        #pragma unroll 8
        for (int i = 0; i < DLOW; ++i) { float v = e[(size_t)i*NE + k]; s += v*v; }
        g_e2_lvl[bl*NE + k] = s;
        if (bl < NBOOK) {       // j == 0 books need inverse column norm for OT
            g_inve0[bl*NE + k] = 1.0f / (sqrtf(s) + EPSF);
        }
    }
}

// x element for lower levels: concat(input_list[j,b,l,:64], q4[b,l,:64])
__device__ __forceinline__ float load_x_low(const float* __restrict__ in,
                                            int j, int b, int l, int c)
{
    if (c < DTOP) return in[((((size_t)j*B + b)*L + l)*DTOP) + c];
    return g_q4[(((size_t)b*L + l)*DTOP) + (c - DTOP)];
}

__device__ __forceinline__ float load_x_top(const float* __restrict__ in,
                                            int b, int l, int c)
{
    return in[((((size_t)4*B + b)*L + l)*DTOP) + c];
}

// ---------------------------------------------------------------------------
// Fused VQ GEMM + argmin + gather + diff (+ OT for level 0)
// Block tile: 32 rows x 512 cols (full codebook). Thread tile: 4 rows x 16 cols
// held as 8 packed f32x2 accumulators. Cols of lane `ln`, pair p:
//   k = p*64 + ln*2 + {0,1}   (bank-conflict-free LDS.64 codebook reads)
// ---------------------------------------------------------------------------
template<int KDIM, bool IS_TOP>
__launch_bounds__(NTHREADS, 2)
__global__ void vq_gemm(const float* __restrict__ input_list,
                        const float* __restrict__ cb_top,
                        const float* __restrict__ cb_lvl,
                        const int*   __restrict__ label,
                        float*       __restrict__ out)
{
    __shared__ __align__(16) float e_s[KT][NE];  // 32 KB
    __shared__ float x_s[BM][KT];                // 2 KB
    __shared__ int   ind_s[BM];
    __shared__ float dist_s[BM];

    const int rb = blockIdx.x;        // row block (0..6)
    const int b  = blockIdx.y;        // sample
    const int s  = blockIdx.z;        // stack index (lower levels); 0 for top
    const int j  = IS_TOP ? 4 : (3 - s);
    const int t  = label[b];
    const int rowbase = rb * BM;
    const int tid  = threadIdx.x;
    const int lane = tid & 31;
    const int w    = tid >> 5;        // warp id = row group

    const float* emb = IS_TOP ? (cb_top + (size_t)t * DTOP * NE)
                              : (cb_lvl + ((size_t)j * NBOOK + t) * DLOW * NE);

    unsigned long long acc[4][8];
    #pragma unroll
    for (int r = 0; r < 4; ++r)
        #pragma unroll
        for (int p = 0; p < 8; ++p) acc[r][p] = 0ull;

    for (int kb = 0; kb < KDIM; kb += KT) {
        // Load codebook tile (KT x 512 floats, contiguous in global)
        {
            const float4* src = (const float4*)(emb + (size_t)kb * NE);
            float4* dst = (float4*)&e_s[0][0];
            #pragma unroll
            for (int it = tid; it < KT*NE/4; it += NTHREADS) dst[it] = src[it];
        }
        // Load x tile (32 rows x KT cols)
        #pragma unroll
        for (int it = tid; it < BM*KT; it += NTHREADS) {
            int r = it / KT, i = it % KT;
            int l = rowbase + r, c = kb + i;
            float v = 0.f;
            if (l < L) v = IS_TOP ? load_x_top(input_list, b, l, c)
                                  : load_x_low(input_list, j, b, l, c);
            x_s[r][i] = v;
        }
        __syncthreads();

        #pragma unroll
        for (int i = 0; i < KT; ++i) {
            unsigned long long xp[4];
            #pragma unroll
            for (int r = 0; r < 4; ++r) {
                float xv = x_s[w*4 + r][i];
                asm("mov.b64 %0, {%1,%1};" : "=l"(xp[r]) : "f"(xv));
            }
            #pragma unroll
            for (int p = 0; p < 8; ++p) {
                unsigned long long ev =
                    *(const unsigned long long*)&e_s[i][p*64 + lane*2];
                #pragma unroll
                for (int r = 0; r < 4; ++r)
                    asm("fma.rn.f32x2 %0, %1, %2, %0;"
                        : "+l"(acc[r][p]) : "l"(xp[r]), "l"(ev));
            }
        }
        __syncthreads();
    }

    // ---- Epilogue ----
    const float* e2p = IS_TOP ? (g_e2_top + (size_t)t * NE)
                              : (g_e2_lvl + ((size_t)j * NBOOK + t) * NE);
    float e2v[16];
    #pragma unroll
    for (int p = 0; p < 8; ++p) {
        e2v[2*p]   = e2p[p*64 + lane*2];
        e2v[2*p+1] = e2p[p*64 + lane*2 + 1];
    }
    const bool do_ot = (!IS_TOP) && (j == 0);
    float invev[16];
    if (do_ot) {
        const float* ip = g_inve0 + (size_t)t * NE;
        #pragma unroll
        for (int p = 0; p < 8; ++p) {
            invev[2*p]   = ip[p*64 + lane*2];
            invev[2*p+1] = ip[p*64 + lane*2 + 1];
        }
    }

    #pragma unroll
    for (int r = 0; r < 4; ++r) {
        int row = w*4 + r;
        int l = rowbase + row;
        if (l >= L) continue;     // uniform per warp

        // ||x_l||^2 (warp-parallel, deterministic)
        float s2 = 0.f;
        for (int c = lane; c < KDIM; c += 32) {
            float v = IS_TOP ? load_x_top(input_list, b, l, c)
                             : load_x_low(input_list, j, b, l, c);
            s2 += v * v;
        }
        #pragma unroll
        for (int o = 16; o; o >>= 1) s2 += __shfl_xor_sync(0xffffffffu, s2, o);

        // unpack g = x . e
        float gv[16];
        #pragma unroll
        for (int p = 0; p < 8; ++p)
            asm("mov.b64 {%0,%1}, %2;" : "=f"(gv[2*p]), "=f"(gv[2*p+1])
                                       : "l"(acc[r][p]));

        // argmin over dist-core = e2 - 2g  (jax argmin: first index on ties)
        float bv = 3.4e38f;
        int   bi = NE;
        #pragma unroll
        for (int c = 0; c < 16; ++c) {
            int k = (c >> 1)*64 + lane*2 + (c & 1);
            float v = fmaf(-2.f, gv[c], e2v[c]);
            if (v < bv || (v == bv && k < bi)) { bv = v; bi = k; }
        }
        #pragma unroll
        for (int o = 16; o; o >>= 1) {
            float ov = __shfl_xor_sync(0xffffffffu, bv, o);
            int   oi = __shfl_xor_sync(0xffffffffu, bi, o);
            if (ov < bv || (ov == bv && oi < bi)) { bv = ov; bi = oi; }
        }
        float dist = s2 + bv;   // ||x - q||^2

        if (lane == 0) { ind_s[row] = bi; dist_s[row] = dist; }
        if (!IS_TOP && lane == 0)
            out[ID_OFF + ((size_t)s*B + b)*L + l] = (float)bi;

        if (do_ot) {
            float invx = 1.0f / (sqrtf(s2) + EPSF);
            float m = -3.4e38f;
            #pragma unroll
            for (int c = 0; c < 16; ++c) m = fmaxf(m, gv[c] * INV512);
            #pragma unroll
            for (int o = 16; o; o >>= 1)
                m = fmaxf(m, __shfl_xor_sync(0xffffffffu, m, o));
            float Z = 0.f, S = 0.f;
            #pragma unroll
            for (int c = 0; c < 16; ++c) {
                float pe = expf(gv[c] * INV512 - m);
                Z += pe;
                S += (1.f - gv[c] * invx * invev[c]) * pe;
            }
            #pragma unroll
            for (int o = 16; o; o >>= 1) {
                Z += __shfl_xor_sync(0xffffffffu, Z, o);
                S += __shfl_xor_sync(0xffffffffu, S, o);
            }
            if (lane == 0) out[OT_OFF + (size_t)b*L + l] = S / Z;
        }
    }
    __syncthreads();

    // diff partial (deterministic single-thread sum of 32 row values)
    if (tid == 0) {
        int nval = L - rowbase; if (nval > BM) nval = BM;
        float sum = 0.f;
        for (int r = 0; r < nval; ++r) sum += dist_s[r];
        int lev = IS_TOP ? 4 : j;
        g_diff[(size_t)lev*B*ROWBLOCKS + (size_t)b*ROWBLOCKS + rb] =
            sum * (1.0f / (float)(L * KDIM));
    }

    // Gather quantized codes: q[l][c] = emb[c*NE + ind[l]]
    const int OD = IS_TOP ? DTOP : DLOW;
    for (int it = tid; it < BM*OD; it += NTHREADS) {
        int r = it / OD, c = it % OD;
        int l = rowbase + r;
        if (l >= L) continue;
        float v = emb[(size_t)c * NE + ind_s[r]];
        if (IS_TOP)
            g_q4[((size_t)b*L + l)*DTOP + c] = v;
        else
            out[QUANT_OFF + (((size_t)s*B + b)*L + l)*DLOW + c] = v;
    }
}

// Deterministic reduction of diff partials
__global__ void diff_reduce(float* __restrict__ out)
{
    __shared__ float sh[256];
    float v = 0.f;
    for (int i = threadIdx.x; i < 5*B*ROWBLOCKS; i += 256) v += g_diff[i];
    sh[threadIdx.x] = v;
    __syncthreads();
    for (int st = 128; st; st >>= 1) {
        if (threadIdx.x < st) sh[threadIdx.x] += sh[threadIdx.x + st];
        __syncthreads();
    }
    if (threadIdx.x == 0) out[DIFF_OFF] = sh[0];
}

extern "C" void kernel_launch(void* const* d_in, const int* in_sizes, int n_in,
                              void* d_out, int out_size)
{
    const float* input_list = nullptr;
    const float* cb_top     = nullptr;
    const float* cb_lvl     = nullptr;
    const int*   label      = nullptr;

    for (int i = 0; i < n_in; ++i) {
        switch (in_sizes[i]) {
            case 8028160: input_list = (const float*)d_in[i]; break;  // (5,128,196,64)
            case 491520:  cb_top     = (const float*)d_in[i]; break;  // (15,64,512)
            case 3932160: cb_lvl     = (const float*)d_in[i]; break;  // (4,15,128,512)
            case 128:     label      = (const int*)  d_in[i]; break;  // (128,)
        }
    }
    if (!input_list || !cb_top || !cb_lvl || !label) return;

    float* out = (float*)d_out;

    norms_kernel<<<NBOOK + 4*NBOOK, NE>>>(cb_top, cb_lvl);
    vq_gemm<DTOP, true ><<<dim3(ROWBLOCKS, B, 1), NTHREADS>>>(input_list, cb_top, cb_lvl, label, out);
    vq_gemm<DLOW, false><<<dim3(ROWBLOCKS, B, 4), NTHREADS>>>(input_list, cb_top, cb_lvl, label, out);
    diff_reduce<<<1, 256>>>(out);
}